// round 10
// baseline (speedup 1.0000x reference)
#include <cuda_runtime.h>
#include <cuda_bf16.h>
#include <math_constants.h>

// Problem constants
#define B       16
#define C       64
#define HW      4096
#define K       1024
#define NPIX    65536
#define QSIZE   4194304
#define OFF_LOSS 4194304
#define OFF_PERP 4194305
#define OFF_IDX  4194306
#define OFF_ENC  4259842          // *4B is 8B-aligned -> float2 stores ok
#define PPB 128                   // 4 warps
#define MPX 64                    // pixels per block
#define NBLOCKS (NPIX / MPX)      // 1024
#define CPT 128                   // codes per tile
#define NTILES (K / CPT)          // 8
#define XPAD 72
#define WPAD 72
#define MAXCAND 32

// Scratch (device globals; no allocation allowed)
__device__ int   d_counts[K];             // zero at load; re-zeroed by vq_fin
__device__ float d_loss_partial[NBLOCKS];
__device__ float d_wsq[K];
__device__ __nv_bfloat16 d_wbf[K * C];

// m16n8k16 row.col bf16 MMA, fp32 accumulate (in-place)
__device__ __forceinline__ void mma_bf16(float& c0, float& c1, float& c2, float& c3,
                                         unsigned a0, unsigned a1, unsigned a2, unsigned a3,
                                         unsigned b0, unsigned b1) {
    asm volatile(
        "mma.sync.aligned.m16n8k16.row.col.f32.bf16.bf16.f32 "
        "{%0,%1,%2,%3},{%4,%5,%6,%7},{%8,%9},{%0,%1,%2,%3};"
        : "+f"(c0), "+f"(c1), "+f"(c2), "+f"(c3)
        : "r"(a0), "r"(a1), "r"(a2), "r"(a3), "r"(b0), "r"(b1));
}

// ---------------------------------------------------------------------------
// Prep: warp-per-code ||w||^2 + bf16 copy.  256 blocks x 128 (4 codes/block).
// wsq reorder noise ~1e-12 << 7.6e-6 decision grid (sub-ulp safe).
// ---------------------------------------------------------------------------
__global__ void vq_prep(const float* __restrict__ weight) {
    int w = threadIdx.x >> 5, l = threadIdx.x & 31;
    int k = blockIdx.x * 4 + w;
    float2 v = ((const float2*)(weight + (size_t)k * C))[l];
    ((__nv_bfloat162*)d_wbf)[(size_t)k * 32 + l] = __floats2bfloat162_rn(v.x, v.y);
    float s = __fadd_rn(__fmul_rn(v.x, v.x), __fmul_rn(v.y, v.y));
#pragma unroll
    for (int o = 16; o > 0; o >>= 1) s += __shfl_xor_sync(0xFFFFFFFFu, s, o);
    if (l == 0) d_wsq[k] = s;
}

// ---------------------------------------------------------------------------
// Main: SINGLE bf16 HMMA pass; per-tile stale-threshold candidate collection
// (superset of the final-threshold set -> sound); exact rescore; cheap
// block-cooperative fallback on list overflow.
// Exact path byte-identical to the R2..R9 passing pipeline.
// ---------------------------------------------------------------------------
__global__ __launch_bounds__(PPB) void vq_main(const float* __restrict__ in,
                                               const float* __restrict__ weight,
                                               float* __restrict__ out) {
    __shared__ __nv_bfloat16 xbf[MPX][XPAD];
    __shared__ __nv_bfloat16 wbf[CPT][WPAD];
    __shared__ float wsq_s[K];
    __shared__ float X_s[MPX], S_s[MPX], D0_s[MPX];
    __shared__ int   candCnt[MPX];
    __shared__ short candL[MPX][MAXCAND];
    __shared__ int   finI[MPX];
    __shared__ float redL[4];
    __shared__ float ovD[4];  __shared__ int ovK[4];
    __shared__ int   ovList[MPX]; __shared__ int ovCnt;

    const int t    = threadIdx.x;
    const int lane = t & 31;
    const int wid  = t >> 5;
    const int q    = lane & 3;
    const int r    = lane >> 2;
    const int b    = blockIdx.x >> 6;
    const int p0   = (blockIdx.x & 63) * MPX;
    const float* xin = in + (size_t)b * C * HW + p0;

    // ---- x -> bf16 tile ----
#pragma unroll
    for (int i = 0; i < 32; i++) {
        int e = i * PPB + t;
        int px = e & 63, c = e >> 6;
        xbf[px][c] = __float2bfloat16(xin[(size_t)c * HW + px]);
    }
#pragma unroll
    for (int i = 0; i < 8; i++) wsq_s[i * PPB + t] = d_wsq[i * PPB + t];
    if (t < MPX) candCnt[t] = 0;
    if (t == 0) ovCnt = 0;
    __syncthreads();

    // ---- per-pixel exact X (sequential, tie-deciding), S=sum|x|, seed d0 ----
    if (t < MPX) {
        float X = 0.f, S = 0.f, m0 = 0.f;
#pragma unroll
        for (int c = 0; c < C; c++) {
            float v = xin[(size_t)c * HW + t];
            X = __fadd_rn(X, __fmul_rn(v, v));
            S += fabsf(v);
            m0 = fmaf(v, weight[c], m0);          // code 0 dot (exact-ish seed)
        }
        X_s[t] = X; S_s[t] = S;
        D0_s[t] = X + wsq_s[0] - 2.f * m0;
    }

    // ---- A fragments: warp wid owns pixels [16*wid, +16) ----
    const int rbase = wid * 16 + r;
    unsigned a[4][4];
#pragma unroll
    for (int k0i = 0; k0i < 4; k0i++) {
        int k0 = k0i * 16;
        a[k0i][0] = *(const unsigned*)&xbf[rbase][k0 + 2 * q];
        a[k0i][1] = *(const unsigned*)&xbf[rbase + 8][k0 + 2 * q];
        a[k0i][2] = *(const unsigned*)&xbf[rbase][k0 + 2 * q + 8];
        a[k0i][3] = *(const unsigned*)&xbf[rbase + 8][k0 + 2 * q + 8];
    }
    __syncthreads();
    // margins: 4E + 1e-4, E = 2^-7 * (1/1024) * sum|x|
    const float marg0 = 4.f * (S_s[rbase] * 7.62939453e-6f) + 1e-4f;
    const float marg1 = 4.f * (S_s[rbase + 8] * 7.62939453e-6f) + 1e-4f;
    float thr0 = D0_s[rbase] + 2.f * marg0;       // seed thresholds (>= final)
    float thr1 = D0_s[rbase + 8] + 2.f * marg1;
    float pixMin0 = CUDART_INF_F, pixMin1 = CUDART_INF_F;

    float2* encz = (float2*)(out + OFF_ENC + (size_t)blockIdx.x * MPX * K);
    const float2 z2 = make_float2(0.f, 0.f);

    // =========== SINGLE PASS: stale-threshold collection ===========
#pragma unroll 1
    for (int tile = 0; tile < NTILES; tile++) {
        __syncthreads();
#pragma unroll
        for (int i = 0; i < 32; i++) {
            int e = i * PPB + t;
            int cp = e & 31, code = e >> 5;
            *(unsigned*)&wbf[code][2 * cp] =
                ((const unsigned*)d_wbf)[((size_t)tile * CPT + code) * 32 + cp];
        }
        __syncthreads();
        // enc zeroing rides under the MMAs (32KB per tile)
#pragma unroll
        for (int i = 0; i < 32; i++) encz[tile * 4096 + i * PPB + t] = z2;

        float tmin0 = CUDART_INF_F, tmin1 = CUDART_INF_F;
#pragma unroll 1
        for (int nc = 0; nc < 16; nc++) {
            const int kb = tile * CPT + nc * 8;
            const int cr = nc * 8 + r;
            float c0 = 0.f, c1 = 0.f, c2 = 0.f, c3 = 0.f;
#pragma unroll
            for (int k0i = 0; k0i < 4; k0i++) {
                unsigned b0 = *(const unsigned*)&wbf[cr][k0i * 16 + 2 * q];
                unsigned b1 = *(const unsigned*)&wbf[cr][k0i * 16 + 2 * q + 8];
                mma_bf16(c0, c1, c2, c3, a[k0i][0], a[k0i][1], a[k0i][2], a[k0i][3], b0, b1);
            }
            float w0 = wsq_s[kb + 2 * q], w1 = wsq_s[kb + 2 * q + 1];
            float d00 = fmaf(-2.f, c0, w0), d01 = fmaf(-2.f, c1, w1);
            float d10 = fmaf(-2.f, c2, w0), d11 = fmaf(-2.f, c3, w1);
            tmin0 = fminf(tmin0, fminf(d00, d01));
            tmin1 = fminf(tmin1, fminf(d10, d11));
            if (d00 <= thr0) { int p = atomicAdd(&candCnt[rbase], 1);     if (p < MAXCAND) candL[rbase][p]     = (short)(kb + 2 * q); }
            if (d01 <= thr0) { int p = atomicAdd(&candCnt[rbase], 1);     if (p < MAXCAND) candL[rbase][p]     = (short)(kb + 2 * q + 1); }
            if (d10 <= thr1) { int p = atomicAdd(&candCnt[rbase + 8], 1); if (p < MAXCAND) candL[rbase + 8][p] = (short)(kb + 2 * q); }
            if (d11 <= thr1) { int p = atomicAdd(&candCnt[rbase + 8], 1); if (p < MAXCAND) candL[rbase + 8][p] = (short)(kb + 2 * q + 1); }
        }
        // per-tile pixel-min + monotone threshold tightening (4 shfls/tile)
        tmin0 = fminf(tmin0, __shfl_xor_sync(0xFFFFFFFFu, tmin0, 1));
        tmin0 = fminf(tmin0, __shfl_xor_sync(0xFFFFFFFFu, tmin0, 2));
        tmin1 = fminf(tmin1, __shfl_xor_sync(0xFFFFFFFFu, tmin1, 1));
        tmin1 = fminf(tmin1, __shfl_xor_sync(0xFFFFFFFFu, tmin1, 2));
        pixMin0 = fminf(pixMin0, tmin0);
        pixMin1 = fminf(pixMin1, tmin1);
        thr0 = fminf(thr0, pixMin0 + marg0);
        thr1 = fminf(thr1, pixMin1 + marg1);
    }
    __syncthreads();

    // ---- overflow list (rare) ----
    if (t < MPX && candCnt[t] > MAXCAND) { int p = atomicAdd(&ovCnt, 1); ovList[p] = t; }
    __syncthreads();

    // =================== exact rescore (reference rounding) ===================
    if (t < MPX && candCnt[t] <= MAXCAND) {
        const float X = X_s[t];
        float best = CUDART_INF_F; int bk = 0;
        const int cnt = candCnt[t];
        for (int i = 0; i < cnt; i++) {
            int k = candL[t][i];
            const float* wk = weight + (size_t)k * C;
            float m = 0.f;
#pragma unroll
            for (int c = 0; c < C; c++) m = fmaf(xin[(size_t)c * HW + t], wk[c], m);
            float d = __fsub_rn(__fadd_rn(X, wsq_s[k]), __fadd_rn(m, m));
            if (d < best || (d == best && k < bk)) { best = d; bk = k; }
        }
        finI[t] = bk;
    }
    __syncthreads();

    // ---- block-cooperative fallback for overflow pixels (~3us each) ----
    for (int i = 0; i < ovCnt; i++) {
        const int px = ovList[i];
        const float X = X_s[px];
        float bd = CUDART_INF_F; int bk = 0;
#pragma unroll 1
        for (int kk = 0; kk < 8; kk++) {
            int k = t * 8 + kk;
            const float* wk = weight + (size_t)k * C;
            float m = 0.f;
#pragma unroll
            for (int c = 0; c < C; c++) m = fmaf(xin[(size_t)c * HW + px], wk[c], m);
            float d = __fsub_rn(__fadd_rn(X, wsq_s[k]), __fadd_rn(m, m));
            if (d < bd || (d == bd && k < bk)) { bd = d; bk = k; }
        }
#pragma unroll
        for (int o = 16; o > 0; o >>= 1) {
            float od = __shfl_down_sync(0xFFFFFFFFu, bd, o);
            int   ok = __shfl_down_sync(0xFFFFFFFFu, bk, o);
            if (od < bd || (od == bd && ok < bk)) { bd = od; bk = ok; }
        }
        if (lane == 0) { ovD[wid] = bd; ovK[wid] = bk; }
        __syncthreads();
        if (t == 0) {
            float fd = ovD[0]; int fk = ovK[0];
#pragma unroll
            for (int g = 1; g < 4; g++)
                if (ovD[g] < fd || (ovD[g] == fd && ovK[g] < fk)) { fd = ovD[g]; fk = ovK[g]; }
            finI[px] = fk;
        }
        __syncthreads();
    }

    // =================== epilogue ===================
    {
        const int px = t & 63;
        const int hf = t >> 6;                   // channel half
        const int bk = finI[px];
        const float* wb = weight + (size_t)bk * C + hf * 32;
        const float* xi = xin + (size_t)hf * 32 * HW + px;
        float* outq = out + (size_t)b * C * HW + (size_t)hf * 32 * HW + p0 + px;
        float lsum = 0.f;
#pragma unroll
        for (int c = 0; c < 32; c++) {
            float xv = xi[(size_t)c * HW];
            float dd = __fsub_rn(wb[c], xv);
            outq[(size_t)c * HW] = __fadd_rn(xv, dd);   // STE
            lsum = fmaf(dd, dd, lsum);
        }
        if (t < MPX) {
            const int n = blockIdx.x * MPX + t;
            out[OFF_IDX + n] = (float)finI[t];
            out[OFF_ENC + (size_t)n * K + finI[t]] = 1.0f;
            atomicAdd(&d_counts[finI[t]], 1);
        }
#pragma unroll
        for (int o = 16; o > 0; o >>= 1) lsum += __shfl_down_sync(0xFFFFFFFFu, lsum, o);
        if ((t & 31) == 0) redL[t >> 5] = lsum;
        __syncthreads();
        if (t == 0) d_loss_partial[blockIdx.x] = (redL[0] + redL[1]) + (redL[2] + redL[3]);
    }
}

// ---------------------------------------------------------------------------
// Finalize: loss + perplexity; re-zeroes d_counts for the next graph replay.
// ---------------------------------------------------------------------------
__global__ void vq_fin(float* __restrict__ out) {
    __shared__ float sh[K];
    __shared__ float sh2[NBLOCKS];
    int t = threadIdx.x;                  // 1024

    int cnt = d_counts[t];
    d_counts[t] = 0;
    float pr = (float)cnt * (1.0f / (float)NPIX);
    sh[t] = pr * logf(pr + 1e-10f);
    sh2[t] = d_loss_partial[t];
    __syncthreads();

    for (int s = K / 2; s > 0; s >>= 1) {
        if (t < s) { sh[t] += sh[t + s]; sh2[t] += sh2[t + s]; }
        __syncthreads();
    }
    if (t == 0) {
        out[OFF_LOSS] = 0.25f * sh2[0] / (float)QSIZE;
        out[OFF_PERP] = expf(-sh[0]);
    }
}

// ---------------------------------------------------------------------------
extern "C" void kernel_launch(void* const* d_in, const int* in_sizes, int n_in,
                              void* d_out, int out_size) {
    const float* in     = (const float*)d_in[0];
    const float* weight = (const float*)d_in[1];
    float* out = (float*)d_out;

    vq_prep<<<256, 128>>>(weight);
    vq_main<<<NBLOCKS, PPB>>>(in, weight, out);
    vq_fin<<<1, K>>>(out);
}

// round 11
// speedup vs baseline: 21.3498x; 21.3498x over previous
#include <cuda_runtime.h>
#include <cuda_bf16.h>
#include <math_constants.h>

// Problem constants
#define B       16
#define C       64
#define HW      4096
#define K       1024
#define NPIX    65536
#define QSIZE   4194304
#define OFF_LOSS 4194304
#define OFF_PERP 4194305
#define OFF_IDX  4194306
#define OFF_ENC  4259842          // *4B is 8B-aligned -> float2 stores ok
#define PPB 128                   // 4 warps
#define MPX 64                    // pixels per block
#define NBLOCKS (NPIX / MPX)      // 1024
#define CPT 128                   // codes per tile
#define NTILES (K / CPT)          // 8
#define XPAD 72
#define WPAD 72
#define MAXCAND 32

// Scratch (device globals; no allocation allowed)
__device__ int   d_counts[K];             // zero at load; re-zeroed by vq_fin
__device__ float d_loss_partial[NBLOCKS];
__device__ float d_wsq[K];
__device__ __nv_bfloat16 d_wbf[K * C];

// m16n8k16 row.col bf16 MMA, fp32 accumulate (in-place)
__device__ __forceinline__ void mma_bf16(float& c0, float& c1, float& c2, float& c3,
                                         unsigned a0, unsigned a1, unsigned a2, unsigned a3,
                                         unsigned b0, unsigned b1) {
    asm volatile(
        "mma.sync.aligned.m16n8k16.row.col.f32.bf16.bf16.f32 "
        "{%0,%1,%2,%3},{%4,%5,%6,%7},{%8,%9},{%0,%1,%2,%3};"
        : "+f"(c0), "+f"(c1), "+f"(c2), "+f"(c3)
        : "r"(a0), "r"(a1), "r"(a2), "r"(a3), "r"(b0), "r"(b1));
}

// ---------------------------------------------------------------------------
// Prep: warp-per-code ||w||^2 + bf16 copy (measured 4.7us).
// ---------------------------------------------------------------------------
__global__ void vq_prep(const float* __restrict__ weight) {
    int w = threadIdx.x >> 5, l = threadIdx.x & 31;
    int k = blockIdx.x * 4 + w;
    float2 v = ((const float2*)(weight + (size_t)k * C))[l];
    ((__nv_bfloat162*)d_wbf)[(size_t)k * 32 + l] = __floats2bfloat162_rn(v.x, v.y);
    float s = __fadd_rn(__fmul_rn(v.x, v.x), __fmul_rn(v.y, v.y));
#pragma unroll
    for (int o = 16; o > 0; o >>= 1) s += __shfl_xor_sync(0xFFFFFFFFu, s, o);
    if (l == 0) d_wsq[k] = s;
}

// ---------------------------------------------------------------------------
// Main: SINGLE bf16 HMMA pass. Candidate test uses LANE-LOCAL running min
// (updated before the test -> threshold >= final threshold everywhere ->
// collected set is a superset of the true candidate set). Per-tile shfl
// tightens lanes to the pixel min. Exact rescore byte-identical to the
// R2..R8 passing pipeline; block-cooperative fallback on overflow.
// ---------------------------------------------------------------------------
__global__ __launch_bounds__(PPB) void vq_main(const float* __restrict__ in,
                                               const float* __restrict__ weight,
                                               float* __restrict__ out) {
    __shared__ __nv_bfloat16 xbf[MPX][XPAD];
    __shared__ __nv_bfloat16 wbf[CPT][WPAD];
    __shared__ float wsq_s[K];
    __shared__ float X_s[MPX];
    __shared__ int   candCnt[MPX];
    __shared__ short candL[MPX][MAXCAND];
    __shared__ int   finI[MPX];
    __shared__ float redL[4];
    __shared__ float ovD[4];  __shared__ int ovK[4];
    __shared__ int   ovList[MPX]; __shared__ int ovCnt;

    const int t    = threadIdx.x;
    const int lane = t & 31;
    const int wid  = t >> 5;
    const int q    = lane & 3;
    const int r    = lane >> 2;
    const int b    = blockIdx.x >> 6;
    const int p0   = (blockIdx.x & 63) * MPX;
    const float* xin = in + (size_t)b * C * HW + p0;

    // ---- x -> bf16 tile ----
#pragma unroll
    for (int i = 0; i < 32; i++) {
        int e = i * PPB + t;
        int px = e & 63, c = e >> 6;
        xbf[px][c] = __float2bfloat16(xin[(size_t)c * HW + px]);
    }
#pragma unroll
    for (int i = 0; i < 8; i++) wsq_s[i * PPB + t] = d_wsq[i * PPB + t];
    if (t < MPX) candCnt[t] = 0;
    if (t == 0) ovCnt = 0;
    __syncthreads();

    // ---- per-pixel exact X (sequential, tie-deciding) + margin ----
    float margT = 0.f;
    if (t < MPX) {
        float X = 0.f, S = 0.f;
#pragma unroll
        for (int c = 0; c < C; c++) {
            float v = xin[(size_t)c * HW + t];
            X = __fadd_rn(X, __fmul_rn(v, v));
            S += fabsf(v);
        }
        X_s[t] = X;
        margT = 4.f * (S * 7.62939453e-6f) + 1e-4f;   // 4E + 1e-4
    }
    // distribute margins to the fragment owners via shmem (reuse redL? no; use xbf pad row)
    __shared__ float marg_s[MPX];
    if (t < MPX) marg_s[t] = margT;

    // ---- A fragments: warp wid owns pixels [16*wid, +16) ----
    const int rbase = wid * 16 + r;
    unsigned a[4][4];
#pragma unroll
    for (int k0i = 0; k0i < 4; k0i++) {
        int k0 = k0i * 16;
        a[k0i][0] = *(const unsigned*)&xbf[rbase][k0 + 2 * q];
        a[k0i][1] = *(const unsigned*)&xbf[rbase + 8][k0 + 2 * q];
        a[k0i][2] = *(const unsigned*)&xbf[rbase][k0 + 2 * q + 8];
        a[k0i][3] = *(const unsigned*)&xbf[rbase + 8][k0 + 2 * q + 8];
    }
    __syncthreads();
    const float marg0 = marg_s[rbase];
    const float marg1 = marg_s[rbase + 8];

    // lane-local running mins (>= pixel min at all times -> sound)
    float rm0 = CUDART_INF_F, rm1 = CUDART_INF_F;

    float2* encz = (float2*)(out + OFF_ENC + (size_t)blockIdx.x * MPX * K);
    const float2 z2 = make_float2(0.f, 0.f);

    // =========== SINGLE PASS ===========
#pragma unroll 1
    for (int tile = 0; tile < NTILES; tile++) {
        __syncthreads();
#pragma unroll
        for (int i = 0; i < 32; i++) {
            int e = i * PPB + t;
            int cp = e & 31, code = e >> 5;
            *(unsigned*)&wbf[code][2 * cp] =
                ((const unsigned*)d_wbf)[((size_t)tile * CPT + code) * 32 + cp];
        }
        __syncthreads();
        // enc zeroing rides under the MMAs (32KB per tile)
#pragma unroll
        for (int i = 0; i < 32; i++) encz[tile * 4096 + i * PPB + t] = z2;

#pragma unroll 1
        for (int nc = 0; nc < 16; nc++) {
            const int kb = tile * CPT + nc * 8;
            const int cr = nc * 8 + r;
            float c0 = 0.f, c1 = 0.f, c2 = 0.f, c3 = 0.f;
#pragma unroll
            for (int k0i = 0; k0i < 4; k0i++) {
                unsigned b0 = *(const unsigned*)&wbf[cr][k0i * 16 + 2 * q];
                unsigned b1 = *(const unsigned*)&wbf[cr][k0i * 16 + 2 * q + 8];
                mma_bf16(c0, c1, c2, c3, a[k0i][0], a[k0i][1], a[k0i][2], a[k0i][3], b0, b1);
            }
            float w0 = wsq_s[kb + 2 * q], w1 = wsq_s[kb + 2 * q + 1];
            float d00 = fmaf(-2.f, c0, w0), d01 = fmaf(-2.f, c1, w1);
            float d10 = fmaf(-2.f, c2, w0), d11 = fmaf(-2.f, c3, w1);
            // update lane-local runmin FIRST, then test (still a superset)
            rm0 = fminf(rm0, fminf(d00, d01));
            rm1 = fminf(rm1, fminf(d10, d11));
            float t0 = rm0 + marg0, t1 = rm1 + marg1;
            if (d00 <= t0) { int p = atomicAdd(&candCnt[rbase], 1);     if (p < MAXCAND) candL[rbase][p]     = (short)(kb + 2 * q); }
            if (d01 <= t0) { int p = atomicAdd(&candCnt[rbase], 1);     if (p < MAXCAND) candL[rbase][p]     = (short)(kb + 2 * q + 1); }
            if (d10 <= t1) { int p = atomicAdd(&candCnt[rbase + 8], 1); if (p < MAXCAND) candL[rbase + 8][p] = (short)(kb + 2 * q); }
            if (d11 <= t1) { int p = atomicAdd(&candCnt[rbase + 8], 1); if (p < MAXCAND) candL[rbase + 8][p] = (short)(kb + 2 * q + 1); }
        }
        // per-tile: tighten all lanes to the pixel min (4 shfls per tile)
        rm0 = fminf(rm0, __shfl_xor_sync(0xFFFFFFFFu, rm0, 1));
        rm0 = fminf(rm0, __shfl_xor_sync(0xFFFFFFFFu, rm0, 2));
        rm1 = fminf(rm1, __shfl_xor_sync(0xFFFFFFFFu, rm1, 1));
        rm1 = fminf(rm1, __shfl_xor_sync(0xFFFFFFFFu, rm1, 2));
    }
    __syncthreads();

    // ---- overflow list (rare now) ----
    if (t < MPX && candCnt[t] > MAXCAND) { int p = atomicAdd(&ovCnt, 1); ovList[p] = t; }
    __syncthreads();

    // =================== exact rescore (reference rounding) ===================
    if (t < MPX && candCnt[t] <= MAXCAND) {
        const float X = X_s[t];
        float best = CUDART_INF_F; int bk = 0;
        const int cnt = candCnt[t];
        for (int i = 0; i < cnt; i++) {
            int k = candL[t][i];
            const float* wk = weight + (size_t)k * C;
            float m = 0.f;
#pragma unroll
            for (int c = 0; c < C; c++) m = fmaf(xin[(size_t)c * HW + t], wk[c], m);
            float d = __fsub_rn(__fadd_rn(X, wsq_s[k]), __fadd_rn(m, m));
            if (d < best || (d == best && k < bk)) { best = d; bk = k; }
        }
        finI[t] = bk;
    }
    __syncthreads();

    // ---- block-cooperative fallback for overflow pixels (~3us each) ----
    for (int i = 0; i < ovCnt; i++) {
        const int px = ovList[i];
        const float X = X_s[px];
        float bd = CUDART_INF_F; int bk = 0;
#pragma unroll 1
        for (int kk = 0; kk < 8; kk++) {
            int k = t * 8 + kk;
            const float* wk = weight + (size_t)k * C;
            float m = 0.f;
#pragma unroll
            for (int c = 0; c < C; c++) m = fmaf(xin[(size_t)c * HW + px], wk[c], m);
            float d = __fsub_rn(__fadd_rn(X, wsq_s[k]), __fadd_rn(m, m));
            if (d < bd || (d == bd && k < bk)) { bd = d; bk = k; }
        }
#pragma unroll
        for (int o = 16; o > 0; o >>= 1) {
            float od = __shfl_down_sync(0xFFFFFFFFu, bd, o);
            int   ok = __shfl_down_sync(0xFFFFFFFFu, bk, o);
            if (od < bd || (od == bd && ok < bk)) { bd = od; bk = ok; }
        }
        if (lane == 0) { ovD[wid] = bd; ovK[wid] = bk; }
        __syncthreads();
        if (t == 0) {
            float fd = ovD[0]; int fk = ovK[0];
#pragma unroll
            for (int g = 1; g < 4; g++)
                if (ovD[g] < fd || (ovD[g] == fd && ovK[g] < fk)) { fd = ovD[g]; fk = ovK[g]; }
            finI[px] = fk;
        }
        __syncthreads();
    }

    // =================== epilogue ===================
    {
        const int px = t & 63;
        const int hf = t >> 6;                   // channel half
        const int bk = finI[px];
        const float* wb = weight + (size_t)bk * C + hf * 32;
        const float* xi = xin + (size_t)hf * 32 * HW + px;
        float* outq = out + (size_t)b * C * HW + (size_t)hf * 32 * HW + p0 + px;
        float lsum = 0.f;
#pragma unroll
        for (int c = 0; c < 32; c++) {
            float xv = xi[(size_t)c * HW];
            float dd = __fsub_rn(wb[c], xv);
            outq[(size_t)c * HW] = __fadd_rn(xv, dd);   // STE
            lsum = fmaf(dd, dd, lsum);
        }
        if (t < MPX) {
            const int n = blockIdx.x * MPX + t;
            out[OFF_IDX + n] = (float)finI[t];
            out[OFF_ENC + (size_t)n * K + finI[t]] = 1.0f;
            atomicAdd(&d_counts[finI[t]], 1);
        }
#pragma unroll
        for (int o = 16; o > 0; o >>= 1) lsum += __shfl_down_sync(0xFFFFFFFFu, lsum, o);
        if ((t & 31) == 0) redL[t >> 5] = lsum;
        __syncthreads();
        if (t == 0) d_loss_partial[blockIdx.x] = (redL[0] + redL[1]) + (redL[2] + redL[3]);
    }
}

// ---------------------------------------------------------------------------
// Finalize: loss + perplexity; re-zeroes d_counts for the next graph replay.
// ---------------------------------------------------------------------------
__global__ void vq_fin(float* __restrict__ out) {
    __shared__ float sh[K];
    __shared__ float sh2[NBLOCKS];
    int t = threadIdx.x;                  // 1024

    int cnt = d_counts[t];
    d_counts[t] = 0;
    float pr = (float)cnt * (1.0f / (float)NPIX);
    sh[t] = pr * logf(pr + 1e-10f);
    sh2[t] = d_loss_partial[t];
    __syncthreads();

    for (int s = K / 2; s > 0; s >>= 1) {
        if (t < s) { sh[t] += sh[t + s]; sh2[t] += sh2[t + s]; }
        __syncthreads();
    }
    if (t == 0) {
        out[OFF_LOSS] = 0.25f * sh2[0] / (float)QSIZE;
        out[OFF_PERP] = expf(-sh[0]);
    }
}

// ---------------------------------------------------------------------------
extern "C" void kernel_launch(void* const* d_in, const int* in_sizes, int n_in,
                              void* d_out, int out_size) {
    const float* in     = (const float*)d_in[0];
    const float* weight = (const float*)d_in[1];
    float* out = (float*)d_out;

    vq_prep<<<256, 128>>>(weight);
    vq_main<<<NBLOCKS, PPB>>>(in, weight, out);
    vq_fin<<<1, K>>>(out);
}